// round 17
// baseline (speedup 1.0000x reference)
#include <cuda_runtime.h>
#include <cuda_fp16.h>
#include <cstdint>
#include <cstddef>

#define DD   1024
#define HH   4096
#define EE   8
#define NTOK 8192
#define CAP  8192
#define STAGE_BYTES 32768            // 16KB A + 16KB B per stage
#define SMEM_TOKS (3 * STAGE_BYTES)
#define SMEM_SZ   (SMEM_TOKS + 512)

#define NX ((size_t)NTOK * DD)       // 8388608
#define NW ((size_t)EE * DD * HH)    // 33554432
#define NWH (NW / 2)                 // 4 experts' worth of w1

// ---- device scratch (static: no runtime allocation) ----
__device__ int    g_counts[EE];
__device__ int    g_tokens[EE * CAP];
__device__ int    g_slot[NTOK * 2];
__device__ float  g_swt[NTOK * 2];
__device__ __half g_xh[NX];                         // x fp16, 16MB
__device__ __half g_w1h[NW];                        // w1 fp16 [e][d][h], 64MB
__device__ __half g_w2h[NW];                        // w2 fp16 [e][h][d], 64MB
__device__ __half g_h[(size_t)EE * CAP * HH];       // relu(h) fp16, 128MB (sparse use)
__device__ float  g_y[(size_t)EE * CAP * DD];       // per-slot y fp32, 256MB (sparse use)

// ---- helpers ----
__device__ __forceinline__ uint32_t smem_u32(const void* p) {
    uint32_t a;
    asm("{ .reg .u64 t; cvta.to.shared.u64 t, %1; cvt.u32.u64 %0, t; }" : "=r"(a) : "l"(p));
    return a;
}
__device__ __forceinline__ void cp_async16(uint32_t dst, const void* src) {
    asm volatile("cp.async.cg.shared.global [%0], [%1], 16;" :: "r"(dst), "l"(src) : "memory");
}
__device__ __forceinline__ void cp_commit() {
    asm volatile("cp.async.commit_group;" ::: "memory");
}
template <int N>
__device__ __forceinline__ void cp_wait() {
    asm volatile("cp.async.wait_group %0;" :: "n"(N) : "memory");
}
__device__ __forceinline__ void ldsm4(uint32_t r[4], uint32_t addr) {
    asm volatile("ldmatrix.sync.aligned.m8n8.x4.shared.b16 {%0,%1,%2,%3}, [%4];"
                 : "=r"(r[0]), "=r"(r[1]), "=r"(r[2]), "=r"(r[3]) : "r"(addr));
}
__device__ __forceinline__ void ldsm4t(uint32_t r[4], uint32_t addr) {
    asm volatile("ldmatrix.sync.aligned.m8n8.x4.trans.shared.b16 {%0,%1,%2,%3}, [%4];"
                 : "=r"(r[0]), "=r"(r[1]), "=r"(r[2]), "=r"(r[3]) : "r"(addr));
}
__device__ __forceinline__ void mma16816(float c[4], const uint32_t a[4], uint32_t b0, uint32_t b1) {
    asm volatile(
        "mma.sync.aligned.m16n8k16.row.col.f32.f16.f16.f32 "
        "{%0,%1,%2,%3},{%4,%5,%6,%7},{%8,%9},{%0,%1,%2,%3};"
        : "+f"(c[0]), "+f"(c[1]), "+f"(c[2]), "+f"(c[3])
        : "r"(a[0]), "r"(a[1]), "r"(a[2]), "r"(a[3]), "r"(b0), "r"(b1));
}
__device__ __forceinline__ int padded_count(int e) {
    int c = g_counts[e];
    if (c > CAP) c = CAP;
    int p = (c + 127) & ~127;
    return p > CAP ? CAP : p;
}

// ---- zero token lists + counters (router branch, BEFORE router) ----
__global__ void k_zero_lists() {
    int j = blockIdx.x * 256 + threadIdx.x;          // 64 x 256 = 16384 int4
    reinterpret_cast<int4*>(g_tokens)[j] = make_int4(0, 0, 0, 0);
    if (blockIdx.x == 0 && threadIdx.x < EE) g_counts[threadIdx.x] = 0;
}

// ---- generic fp32->fp16 streaming convert ----
__global__ void k_cvt(const float* __restrict__ src, __half* __restrict__ dst) {
    size_t i = ((size_t)blockIdx.x * blockDim.x + threadIdx.x) * 8;
    float4 a = *reinterpret_cast<const float4*>(src + i);
    float4 b = *reinterpret_cast<const float4*>(src + i + 4);
    __half2 h[4];
    h[0] = __floats2half2_rn(a.x, a.y);
    h[1] = __floats2half2_rn(a.z, a.w);
    h[2] = __floats2half2_rn(b.x, b.y);
    h[3] = __floats2half2_rn(b.z, b.w);
    *reinterpret_cast<uint4*>(dst + i) = *reinterpret_cast<uint4*>(h);
}

// ---- router (1 warp per token, fp32 selection) ----
__global__ void k_router(const float* __restrict__ xs, const float* __restrict__ gw) {
    int warp = (int)((blockIdx.x * blockDim.x + threadIdx.x) >> 5);
    int lane = threadIdx.x & 31;
    if (warp >= NTOK) return;

    const float* x = xs + (size_t)warp * DD;
    float xr[32];
#pragma unroll
    for (int i = 0; i < 32; i++) xr[i] = x[lane + 32 * i];

    float logit[EE];
#pragma unroll
    for (int e = 0; e < EE; e++) {
        const float* g = gw + e * DD;
        float a = 0.f;
#pragma unroll
        for (int i = 0; i < 32; i++) a += xr[i] * g[lane + 32 * i];
#pragma unroll
        for (int o = 16; o; o >>= 1) a += __shfl_xor_sync(0xFFFFFFFFu, a, o);
        logit[e] = a;
    }

    if (lane == 0) {
        float v0 = -1e30f, v1 = -1e30f;
        int i0 = 0, i1 = 0;
#pragma unroll
        for (int e = 0; e < EE; e++) {
            float v = logit[e];
            if (v > v0) { v1 = v0; i1 = i0; v0 = v; i0 = e; }
            else if (v > v1) { v1 = v; i1 = e; }
        }
        float e1 = __expf(v1 - v0);
        float s = 1.f + e1;
        float w0 = 1.f / s;
        float w1 = e1 / s;

        int s0 = atomicAdd(&g_counts[i0], 1);
        g_tokens[i0 * CAP + s0] = warp;
        g_slot[warp * 2 + 0] = i0 * CAP + s0;
        g_swt[warp * 2 + 0] = w0;
        int s1 = atomicAdd(&g_counts[i1], 1);
        g_tokens[i1 * CAP + s1] = warp;
        g_slot[warp * 2 + 1] = i1 * CAP + s1;
        g_swt[warp * 2 + 1] = w1;
    }
}

// ---- GEMM1: h = relu(x_gather @ w1). 128x128 tile, BK=64, 3 stages, 2 CTA/SM ----
__global__ __launch_bounds__(256, 2) void k_gemm1(int e0) {
    const int e = e0 + blockIdx.z;
    const int m0 = blockIdx.y * 128;
    if (m0 >= padded_count(e)) return;
    const int n0 = blockIdx.x * 128;
    const int T = DD / 64;  // 16

    extern __shared__ char smem[];
    const uint32_t sb = smem_u32(smem);
    int* toks = (int*)(smem + SMEM_TOKS);
    const int tid = threadIdx.x;

    if (tid < 128) toks[tid] = g_tokens[e * CAP + m0 + tid];
    __syncthreads();

    const __half* bsrc = g_w1h + (size_t)e * DD * HH + n0;

    auto issue = [&](int kt) {
        const int k0 = kt * 64;
        const uint32_t Ab = sb + (kt % 3) * STAGE_BYTES;
        const uint32_t Bb = Ab + 16384;
#pragma unroll
        for (int i = 0; i < 4; i++) {
            int idx = tid + 256 * i;
            int row = idx >> 3, c = idx & 7;
            cp_async16(Ab + row * 128 + ((c ^ (row & 7)) << 4),
                       g_xh + (size_t)toks[row] * DD + k0 + c * 8);
        }
#pragma unroll
        for (int i = 0; i < 4; i++) {
            int idx = tid + 256 * i;
            int row = idx >> 4, c = idx & 15;
            cp_async16(Bb + row * 256 + ((c ^ (row & 7)) << 4),
                       bsrc + (size_t)(k0 + row) * HH + c * 8);
        }
    };

    issue(0); cp_commit();
    issue(1); cp_commit();

    const int lane = tid & 31, wid = tid >> 5;
    const int wm = wid & 1, wn = wid >> 1;  // 2m x 4n, 64x32 each
    const int lrow = lane & 15, lk = lane >> 4;

    float acc[4][4][4];
#pragma unroll
    for (int a = 0; a < 4; a++)
#pragma unroll
        for (int b = 0; b < 4; b++)
#pragma unroll
            for (int c = 0; c < 4; c++) acc[a][b][c] = 0.f;

    for (int kt = 0; kt < T; kt++) {
        cp_wait<1>();
        __syncthreads();
        if (kt + 2 < T) issue(kt + 2);
        cp_commit();

        const uint32_t Ab = sb + (kt % 3) * STAGE_BYTES;
        const uint32_t Bb = Ab + 16384;
#pragma unroll
        for (int ks = 0; ks < 4; ks++) {
            uint32_t a[4][4], b[2][4];
#pragma unroll
            for (int mt = 0; mt < 4; mt++) {
                int row = wm * 64 + mt * 16 + lrow;
                ldsm4(a[mt], Ab + row * 128 + ((((ks << 1) | lk) ^ (row & 7)) << 4));
            }
#pragma unroll
            for (int nt2 = 0; nt2 < 2; nt2++) {
                int krow = ks * 16 + lrow;
                int chunk = wn * 4 + nt2 * 2 + lk;
                ldsm4t(b[nt2], Bb + krow * 256 + ((chunk ^ (krow & 7)) << 4));
            }
#pragma unroll
            for (int mt = 0; mt < 4; mt++)
#pragma unroll
                for (int nt = 0; nt < 4; nt++) {
                    const int nt2 = nt >> 1, sub = nt & 1;
                    mma16816(acc[mt][nt], a[mt], b[nt2][2 * sub], b[nt2][2 * sub + 1]);
                }
        }
    }

    // epilogue: relu -> g_h (fp16)
    const int g = lane >> 2, tg = lane & 3;
#pragma unroll
    for (int mt = 0; mt < 4; mt++) {
        const size_t r0 = (size_t)(e * CAP + m0 + wm * 64 + mt * 16 + g);
        __half* p0 = g_h + r0 * HH + n0;
        __half* p1 = p0 + (size_t)8 * HH;
#pragma unroll
        for (int nt = 0; nt < 4; nt++) {
            const int c = wn * 32 + nt * 8 + tg * 2;
            const float* A = acc[mt][nt];
            *(__half2*)(p0 + c) = __floats2half2_rn(fmaxf(A[0], 0.f), fmaxf(A[1], 0.f));
            *(__half2*)(p1 + c) = __floats2half2_rn(fmaxf(A[2], 0.f), fmaxf(A[3], 0.f));
        }
    }
}

// ---- GEMM2: y = h @ w2. 128x128 tile, BK=64, 3 stages, 2 CTA/SM ----
__global__ __launch_bounds__(256, 2) void k_gemm2(int e0) {
    const int e = e0 + blockIdx.z;
    const int m0 = blockIdx.y * 128;
    if (m0 >= padded_count(e)) return;
    const int n0 = blockIdx.x * 128;
    const int T = HH / 64;  // 64

    extern __shared__ char smem[];
    const uint32_t sb = smem_u32(smem);
    const int tid = threadIdx.x;

    const __half* bsrc = g_w2h + (size_t)e * HH * DD + n0;
    const __half* asrc0 = g_h + (size_t)(e * CAP + m0) * HH;

    auto issue = [&](int kt) {
        const int k0 = kt * 64;
        const uint32_t Ab = sb + (kt % 3) * STAGE_BYTES;
        const uint32_t Bb = Ab + 16384;
#pragma unroll
        for (int i = 0; i < 4; i++) {
            int idx = tid + 256 * i;
            int row = idx >> 3, c = idx & 7;
            cp_async16(Ab + row * 128 + ((c ^ (row & 7)) << 4),
                       asrc0 + (size_t)row * HH + k0 + c * 8);
        }
#pragma unroll
        for (int i = 0; i < 4; i++) {
            int idx = tid + 256 * i;
            int row = idx >> 4, c = idx & 15;
            cp_async16(Bb + row * 256 + ((c ^ (row & 7)) << 4),
                       bsrc + (size_t)(k0 + row) * DD + c * 8);
        }
    };

    issue(0); cp_commit();
    issue(1); cp_commit();

    const int lane = tid & 31, wid = tid >> 5;
    const int wm = wid & 1, wn = wid >> 1;
    const int lrow = lane & 15, lk = lane >> 4;

    float acc[4][4][4];
#pragma unroll
    for (int a = 0; a < 4; a++)
#pragma unroll
        for (int b = 0; b < 4; b++)
#pragma unroll
            for (int c = 0; c < 4; c++) acc[a][b][c] = 0.f;

    for (int kt = 0; kt < T; kt++) {
        cp_wait<1>();
        __syncthreads();
        if (kt + 2 < T) issue(kt + 2);
        cp_commit();

        const uint32_t Ab = sb + (kt % 3) * STAGE_BYTES;
        const uint32_t Bb = Ab + 16384;
#pragma unroll
        for (int ks = 0; ks < 4; ks++) {
            uint32_t a[4][4], b[2][4];
#pragma unroll
            for (int mt = 0; mt < 4; mt++) {
                int row = wm * 64 + mt * 16 + lrow;
                ldsm4(a[mt], Ab + row * 128 + ((((ks << 1) | lk) ^ (row & 7)) << 4));
            }
#pragma unroll
            for (int nt2 = 0; nt2 < 2; nt2++) {
                int krow = ks * 16 + lrow;
                int chunk = wn * 4 + nt2 * 2 + lk;
                ldsm4t(b[nt2], Bb + krow * 256 + ((chunk ^ (krow & 7)) << 4));
            }
#pragma unroll
            for (int mt = 0; mt < 4; mt++)
#pragma unroll
                for (int nt = 0; nt < 4; nt++) {
                    const int nt2 = nt >> 1, sub = nt & 1;
                    mma16816(acc[mt][nt], a[mt], b[nt2][2 * sub], b[nt2][2 * sub + 1]);
                }
        }
    }

    const int g = lane >> 2, tg = lane & 3;
#pragma unroll
    for (int mt = 0; mt < 4; mt++) {
        const size_t r0 = (size_t)(e * CAP + m0 + wm * 64 + mt * 16 + g);
        float* y0 = g_y + r0 * DD + n0;
        float* y1 = y0 + (size_t)8 * DD;
#pragma unroll
        for (int nt = 0; nt < 4; nt++) {
            const int c = wn * 32 + nt * 8 + tg * 2;
            const float* A = acc[mt][nt];
            *(float2*)(y0 + c) = make_float2(A[0], A[1]);
            *(float2*)(y1 + c) = make_float2(A[2], A[3]);
        }
    }
}

// ---- combine: out[t] = w0*y[s0] + w1*y[s1] ----
__global__ __launch_bounds__(256) void k_combine(float* __restrict__ out) {
    const int t = blockIdx.x;
    const int s0 = g_slot[t * 2 + 0];
    const int s1 = g_slot[t * 2 + 1];
    const float w0 = g_swt[t * 2 + 0];
    const float w1 = g_swt[t * 2 + 1];
    const float4 a = ((const float4*)(g_y + (size_t)s0 * DD))[threadIdx.x];
    const float4 b = ((const float4*)(g_y + (size_t)s1 * DD))[threadIdx.x];
    float4 o;
    o.x = w0 * a.x + w1 * b.x;
    o.y = w0 * a.y + w1 * b.y;
    o.z = w0 * a.z + w1 * b.z;
    o.w = w0 * a.w + w1 * b.w;
    ((float4*)(out + (size_t)t * DD))[threadIdx.x] = o;
}

extern "C" void kernel_launch(void* const* d_in, const int* in_sizes, int n_in,
                              void* d_out, int out_size) {
    const float* xs = (const float*)d_in[0];
    const float* gw = (const float*)d_in[1];
    const float* w1 = (const float*)d_in[2];
    const float* w2 = (const float*)d_in[3];
    float* out = (float*)d_out;

    static cudaStream_t sW = nullptr, sRT = nullptr, sG = nullptr;
    static cudaEvent_t evRoot = nullptr, evW1a = nullptr, evW1b = nullptr,
                       evW2 = nullptr, evRT = nullptr, evG1a = nullptr, evG2a = nullptr;
    if (!sW) {
        cudaStreamCreateWithFlags(&sW, cudaStreamNonBlocking);
        cudaStreamCreateWithFlags(&sRT, cudaStreamNonBlocking);
        cudaStreamCreateWithFlags(&sG, cudaStreamNonBlocking);
        cudaEventCreateWithFlags(&evRoot, cudaEventDisableTiming);
        cudaEventCreateWithFlags(&evW1a, cudaEventDisableTiming);
        cudaEventCreateWithFlags(&evW1b, cudaEventDisableTiming);
        cudaEventCreateWithFlags(&evW2, cudaEventDisableTiming);
        cudaEventCreateWithFlags(&evRT, cudaEventDisableTiming);
        cudaEventCreateWithFlags(&evG1a, cudaEventDisableTiming);
        cudaEventCreateWithFlags(&evG2a, cudaEventDisableTiming);
        cudaFuncSetAttribute(k_gemm1, cudaFuncAttributeMaxDynamicSharedMemorySize, SMEM_SZ);
        cudaFuncSetAttribute(k_gemm2, cudaFuncAttributeMaxDynamicSharedMemorySize, SMEM_SZ);
    }

    float* w1hf; cudaGetSymbolAddress((void**)&w1hf, g_w1h);
    float* w2hf; cudaGetSymbolAddress((void**)&w2hf, g_w2h);
    float* xhf;  cudaGetSymbolAddress((void**)&xhf, g_xh);

    // fork
    cudaEventRecord(evRoot, 0);
    cudaStreamWaitEvent(sW, evRoot, 0);
    cudaStreamWaitEvent(sRT, evRoot, 0);
    cudaStreamWaitEvent(sG, evRoot, 0);

    // router branch: zero lists/counters then route
    k_zero_lists<<<64, 256, 0, sRT>>>();
    k_router<<<NTOK / 8, 256, 0, sRT>>>(xs, gw);
    cudaEventRecord(evRT, sRT);

    // weights branch: w1 halves then w2
    k_cvt<<<(int)(NWH / 8 / 256), 256, 0, sW>>>(w1, (__half*)w1hf);
    cudaEventRecord(evW1a, sW);
    k_cvt<<<(int)(NWH / 8 / 256), 256, 0, sW>>>(w1 + NWH, (__half*)w1hf + NWH);
    cudaEventRecord(evW1b, sW);
    k_cvt<<<(int)(NW / 8 / 256), 256, 0, sW>>>(w2, (__half*)w2hf);
    cudaEventRecord(evW2, sW);

    // main: x convert, then g1a (experts 0-3)
    k_cvt<<<(int)(NX / 8 / 256), 256>>>(xs, (__half*)xhf);
    cudaStreamWaitEvent(0, evRT, 0);
    cudaStreamWaitEvent(0, evW1a, 0);
    k_gemm1<<<dim3(HH / 128, CAP / 128, EE / 2), 256, SMEM_SZ>>>(0);
    cudaEventRecord(evG1a, 0);

    // g1b (experts 4-7) on main — serial after g1a (no gemm1 self-concurrency)
    cudaStreamWaitEvent(0, evW1b, 0);
    k_gemm1<<<dim3(HH / 128, CAP / 128, EE / 2), 256, SMEM_SZ>>>(4);

    // g2a (experts 0-3) on sG — overlaps g1b
    cudaStreamWaitEvent(sG, evG1a, 0);
    cudaStreamWaitEvent(sG, evW2, 0);
    k_gemm2<<<dim3(DD / 128, CAP / 128, EE / 2), 256, SMEM_SZ, sG>>>(0);
    cudaEventRecord(evG2a, sG);

    // g2b (experts 4-7) on main after g1b; combine joins both
    cudaStreamWaitEvent(0, evW2, 0);
    k_gemm2<<<dim3(DD / 128, CAP / 128, EE / 2), 256, SMEM_SZ>>>(4);
    cudaStreamWaitEvent(0, evG2a, 0);
    k_combine<<<NTOK, 256>>>(out);
}